// round 13
// baseline (speedup 1.0000x reference)
#include <cuda_runtime.h>
#include <cuda_fp16.h>
#include <cstdint>

#define B_  2
#define C_  256
#define H_  128
#define W_  128
#define HW_ (H_ * W_)
#define NH  32
#define NW  32

// ---------------------------------------------------------------------------
// Static scratch (no runtime allocation allowed).
// ---------------------------------------------------------------------------
__device__ __align__(256) __half g_Wh[3][C_ * C_];                // fp16(W), [O][K]
__device__ __align__(256) __half g_QKV[3][(size_t)B_ * C_ * HW_]; // Q,K,V fp16 [b][c][hw]

// ---------------------------------------------------------------------------
// Helpers
// ---------------------------------------------------------------------------
__device__ __forceinline__ uint32_t smem_u32(const void* p) {
  uint32_t a;
  asm("{ .reg .u64 t; cvta.to.shared.u64 t, %1; cvt.u32.u64 %0, t; }" : "=r"(a) : "l"(p));
  return a;
}

#define CP_ASYNC16(s, g) \
  asm volatile("cp.async.cg.shared.global [%0], [%1], 16;" :: "r"(s), "l"(g))
#define CP_COMMIT() asm volatile("cp.async.commit_group;" ::: "memory")
#define CP_WAIT0()  asm volatile("cp.async.wait_group 0;" ::: "memory")
#define CP_WAIT1()  asm volatile("cp.async.wait_group 1;" ::: "memory")

__device__ __forceinline__ void ldsm_x4(uint32_t* r, uint32_t addr) {
  asm volatile("ldmatrix.sync.aligned.m8n8.x4.shared.b16 {%0,%1,%2,%3}, [%4];"
               : "=r"(r[0]), "=r"(r[1]), "=r"(r[2]), "=r"(r[3]) : "r"(addr));
}
__device__ __forceinline__ void ldsm_x4_t(uint32_t* r, uint32_t addr) {
  asm volatile("ldmatrix.sync.aligned.m8n8.x4.trans.shared.b16 {%0,%1,%2,%3}, [%4];"
               : "=r"(r[0]), "=r"(r[1]), "=r"(r[2]), "=r"(r[3]) : "r"(addr));
}

__device__ __forceinline__ void mma_f16(float* c, const uint32_t* a, const uint32_t* b) {
  asm volatile(
      "mma.sync.aligned.m16n8k16.row.col.f32.f16.f16.f32 "
      "{%0,%1,%2,%3}, {%4,%5,%6,%7}, {%8,%9}, {%0,%1,%2,%3};"
      : "+f"(c[0]), "+f"(c[1]), "+f"(c[2]), "+f"(c[3])
      : "r"(a[0]), "r"(a[1]), "r"(a[2]), "r"(a[3]), "r"(b[0]), "r"(b[1]));
}

// A smem tile: 128 rows x 32 fp16 (64B rows, 4 x 16B chunks, XOR swizzle)
__device__ __forceinline__ uint32_t soff(int r, int c) {
  return (uint32_t)(r * 64 + ((c ^ ((r >> 1) & 3)) << 4));
}
// B smem tile: 32 k-rows x 128 n fp16 (256B rows, 16 x 16B chunks, XOR swizzle)
__device__ __forceinline__ uint32_t boff(int r, int c) {
  return (uint32_t)(r * 256 + ((c ^ (r & 7)) << 4));
}

// ---------------------------------------------------------------------------
// Kernel 0: weights -> fp16 (2 elems/thread, high block count for latency).
// ---------------------------------------------------------------------------
__global__ void __launch_bounds__(256) convert_w_kernel(
    const float* __restrict__ qw, const float* __restrict__ kw,
    const float* __restrict__ vw) {
  int e = (blockIdx.x * 256 + threadIdx.x) * 2;
  int p = e >> 16;
  int r = e & 0xFFFF;
  const float* w = ((p == 0) ? qw : (p == 1) ? kw : vw) + r;
  float2 f = *(const float2*)w;
  *(__half2*)(g_Wh[p] + r) = __floats2half2_rn(f.x, f.y);
}

// ---------------------------------------------------------------------------
// Kernel 1: single-pass fp16 GEMM via mma.sync (HMMA)  [R12 structure].
// ---------------------------------------------------------------------------
__global__ void __launch_bounds__(256, 2) gemm_mma_kernel(
    const float* __restrict__ blue, const float* __restrict__ white,
    const float* __restrict__ qb, const float* __restrict__ kb,
    const float* __restrict__ vb) {
  extern __shared__ char sm[];
  const uint32_t sbase = smem_u32(sm);

  const int tid = threadIdx.x;
  const int lane = tid & 31;
  const int wid = tid >> 5;
  const int wm = wid >> 2;
  const int wn = wid & 3;

  const int z = blockIdx.z;
  const int p = z >> 1;
  const int b = z & 1;
  const int m0 = blockIdx.y * 128;
  const int n0 = blockIdx.x * 128;

  const __half* __restrict__ gA = g_Wh[p] + m0 * C_;
  const float* __restrict__ Xsrc =
      ((p == 0) ? blue : white) + (size_t)b * C_ * HW_ + n0;

  const int stg_ar = tid >> 2;
  const int stg_ac = tid & 3;
  const int stg_br = tid >> 4;
  const int stg_bc = tid & 15;

  float acc[4][4][4];
#pragma unroll
  for (int mt = 0; mt < 4; mt++)
#pragma unroll
    for (int nt = 0; nt < 4; nt++)
#pragma unroll
      for (int e = 0; e < 4; e++) acc[mt][nt][e] = 0.f;

  float4 bf[2][2];

#define ISSUE_A(ks, buf)                                                        \
  {                                                                             \
    const int k0 = (ks) * 32;                                                   \
    _Pragma("unroll")                                                           \
    for (int it = 0; it < 2; it++) {                                            \
      int r = stg_ar + it * 64;                                                 \
      CP_ASYNC16(sbase + (buf) * 16384 + soff(r, stg_ac),                       \
                 gA + r * C_ + k0 + stg_ac * 8);                                \
    }                                                                           \
    CP_COMMIT();                                                                \
  }

#define LDG_B(ks)                                                               \
  {                                                                             \
    const float* bp = Xsrc + (size_t)((ks) * 32) * HW_;                         \
    _Pragma("unroll")                                                           \
    for (int it = 0; it < 2; it++) {                                            \
      const float* q = bp + (size_t)(stg_br + it * 16) * HW_ + stg_bc * 8;      \
      bf[it][0] = *(const float4*)q;                                            \
      bf[it][1] = *(const float4*)(q + 4);                                      \
    }                                                                           \
  }

#define STS_B(buf)                                                              \
  {                                                                             \
    _Pragma("unroll")                                                           \
    for (int it = 0; it < 2; it++) {                                            \
      int r = stg_br + it * 16;                                                 \
      __half2 h[4];                                                             \
      h[0] = __floats2half2_rn(bf[it][0].x, bf[it][0].y);                       \
      h[1] = __floats2half2_rn(bf[it][0].z, bf[it][0].w);                       \
      h[2] = __floats2half2_rn(bf[it][1].x, bf[it][1].y);                       \
      h[3] = __floats2half2_rn(bf[it][1].z, bf[it][1].w);                       \
      *(uint4*)(sm + (buf) * 16384 + 8192 + boff(r, stg_bc)) = *(uint4*)h;      \
    }                                                                           \
  }

  ISSUE_A(0, 0);
  LDG_B(0);

  for (int ks = 0; ks < 8; ks++) {
    const int buf = ks & 1;
    STS_B(buf);
    if (ks + 1 < 8) {
      LDG_B(ks + 1);
      ISSUE_A(ks + 1, buf ^ 1);
      CP_WAIT1();
    } else {
      CP_WAIT0();
    }
    __syncthreads();

    const uint32_t Ab = sbase + buf * 16384;
    const uint32_t Bb = Ab + 8192;

#pragma unroll
    for (int kc = 0; kc < 2; kc++) {
      uint32_t ah[4][4], bh[2][4];
      const int arow = wm * 64 + (lane & 15);
      const int achunk = kc * 2 + (lane >> 4);
#pragma unroll
      for (int mt = 0; mt < 4; mt++) {
        int rr = arow + mt * 16;
        ldsm_x4(ah[mt], Ab + soff(rr, achunk));
      }
      const int brow = kc * 16 + ((lane >> 3) & 1) * 8 + (lane & 7);
#pragma unroll
      for (int bt = 0; bt < 2; bt++) {
        int cb = wn * 4 + bt * 2 + (lane >> 4);
        ldsm_x4_t(bh[bt], Bb + boff(brow, cb));
      }
#pragma unroll
      for (int mt = 0; mt < 4; mt++) {
#pragma unroll
        for (int nt = 0; nt < 4; nt++) {
          mma_f16(acc[mt][nt], ah[mt], &bh[nt >> 1][(nt & 1) * 2]);
        }
      }
    }
    __syncthreads();
  }

  const float* __restrict__ biasp = (p == 0) ? qb : (p == 1) ? kb : vb;
  __half* __restrict__ Out = g_QKV[p] + (size_t)b * C_ * HW_;
  const int mrow_base = m0 + wm * 64 + (lane >> 2);
  const int ncol_base = n0 + wn * 32 + (lane & 3) * 2;

#pragma unroll
  for (int mt = 0; mt < 4; mt++) {
    int mr = mrow_base + mt * 16;
    float bi0 = __ldg(biasp + mr);
    float bi1 = __ldg(biasp + mr + 8);
#pragma unroll
    for (int nt = 0; nt < 4; nt++) {
      int nc = ncol_base + nt * 8;
      *(__half2*)(Out + (size_t)mr * HW_ + nc) =
          __floats2half2_rn(acc[mt][nt][0] + bi0, acc[mt][nt][1] + bi0);
      *(__half2*)(Out + (size_t)(mr + 8) * HW_ + nc) =
          __floats2half2_rn(acc[mt][nt][2] + bi1, acc[mt][nt][3] + bi1);
    }
  }
}

// ---------------------------------------------------------------------------
// Kernel 2: attention with cooperative smem-tiled K/V.
// Block = (32 j, 8 c). Stages 3 token-rows x 8 channels of K and V into smem
// (tokens padded to 48B for conflict-free LDS.128), then per-thread fused
// logit+accumulate pass identical in arithmetic to R12.
// ---------------------------------------------------------------------------
#define ATTN_SMEM (48 * 32 * 24 * 2)   // 48 tiles x 32 tokens x 24 halves x 2B

__global__ void __launch_bounds__(256) attn_kernel(float* __restrict__ out) {
  extern __shared__ __half smem[];
  const int tx = threadIdx.x;                   // 0..31 (j)
  const int ty = threadIdx.y;                   // 0..7  (c within group)
  const int tid = ty * 32 + tx;
  const int i = blockIdx.x;                     // token row
  const int cbase = blockIdx.y * 8;
  const int b = blockIdx.z;

  // ---- cooperative load: K (mat 0) and V (mat 1), rows i-1..i+1 ----
#pragma unroll
  for (int mat = 0; mat < 2; mat++) {
#pragma unroll
    for (int r = 0; r < 3; r++) {
      const int ii = i + r - 1;
      if ((unsigned)ii < (unsigned)NH) {        // uniform per block
#pragma unroll
        for (int u = 0; u < 2; u++) {
          const int it = u * 256 + tid;
          const int c = it >> 6;
          const int seg = it & 63;
          const int h = seg & 3;                // in-token row (lane-minor)
          const int s = seg >> 2;               // 16B segment = 2 tokens
          const __half* g = g_QKV[1 + mat] +
              ((size_t)(b * C_ + cbase + c)) * HW_ + (ii * 4 + h) * W_ + s * 8;
          uint4 v = *(const uint4*)g;
          const int tIdx = (mat * 3 + r) * 8 + c;
          __half* d = smem + (tIdx * 32 + 2 * s) * 24 + h * 4;
          *(uint2*)d        = make_uint2(v.x, v.y);   // token 2s
          *(uint2*)(d + 24) = make_uint2(v.z, v.w);   // token 2s+1
        }
      }
    }
  }
  __syncthreads();

  // ---- per-thread attention ----
  const int c = cbase + ty;
  const size_t base = ((size_t)b * C_ + c) * HW_;
  const __half* __restrict__ Qp = g_QKV[0] + base;
  const int tok = (i * 4) * W_ + tx * 4;

  __half2 qh[8];
  {
    uint2 u0 = *(const uint2*)(Qp + tok);
    uint2 u1 = *(const uint2*)(Qp + tok + W_);
    uint2 u2 = *(const uint2*)(Qp + tok + 2 * W_);
    uint2 u3 = *(const uint2*)(Qp + tok + 3 * W_);
    uint32_t* q32 = (uint32_t*)qh;
    q32[0] = u0.x; q32[1] = u0.y; q32[2] = u1.x; q32[3] = u1.y;
    q32[4] = u2.x; q32[5] = u2.y; q32[6] = u3.x; q32[7] = u3.y;
  }

  float wsum = 0.f;
  float o[16];
#pragma unroll
  for (int e = 0; e < 16; e++) o[e] = 0.f;

#pragma unroll
  for (int n = 0; n < 9; n++) {
    const int r = n / 3;
    const int ii = i + r - 1;
    const int jj = tx + n % 3 - 1;
    if ((unsigned)ii < (unsigned)NH && (unsigned)jj < (unsigned)NW) {
      const __half* kp = smem + (((r) * 8 + ty) * 32 + jj) * 24;
      const __half* vp = smem + (((3 + r) * 8 + ty) * 32 + jj) * 24;
      uint4 k0 = *(const uint4*)kp;
      uint4 k1 = *(const uint4*)(kp + 8);
      uint4 v0 = *(const uint4*)vp;
      uint4 v1 = *(const uint4*)(vp + 8);
      const uint32_t kk[8] = {k0.x, k0.y, k0.z, k0.w, k1.x, k1.y, k1.z, k1.w};
      const uint32_t vv[8] = {v0.x, v0.y, v0.z, v0.w, v1.x, v1.y, v1.z, v1.w};

      __half2 acc = __float2half2_rn(0.f);
#pragma unroll
      for (int h = 0; h < 8; h++)
        acc = __hfma2(qh[h], *(const __half2*)&kk[h], acc);
      const float e = __expf((__low2float(acc) + __high2float(acc)) * 0.25f);
      wsum += e;

#pragma unroll
      for (int h = 0; h < 8; h++) {
        float2 f = __half22float2(*(const __half2*)&vv[h]);
        o[h * 2]     = fmaf(e, f.x, o[h * 2]);
        o[h * 2 + 1] = fmaf(e, f.y, o[h * 2 + 1]);
      }
    }
  }

  const float inv = 1.f / wsum;
#pragma unroll
  for (int e = 0; e < 16; e++) o[e] *= inv;

  float* op = out + base + tok;
#pragma unroll
  for (int r = 0; r < 4; r++)
    *(float4*)(op + r * W_) =
        make_float4(o[r * 4], o[r * 4 + 1], o[r * 4 + 2], o[r * 4 + 3]);
}

// ---------------------------------------------------------------------------
extern "C" void kernel_launch(void* const* d_in, const int* in_sizes, int n_in,
                              void* d_out, int out_size) {
  const float* blue  = (const float*)d_in[0];
  const float* white = (const float*)d_in[1];
  const float* qw    = (const float*)d_in[2];
  const float* qb    = (const float*)d_in[3];
  const float* kw    = (const float*)d_in[4];
  const float* kb    = (const float*)d_in[5];
  const float* vw    = (const float*)d_in[6];
  const float* vb    = (const float*)d_in[7];

  const int smem_bytes = 32768;
  cudaFuncSetAttribute(gemm_mma_kernel, cudaFuncAttributeMaxDynamicSharedMemorySize,
                       smem_bytes);
  cudaFuncSetAttribute(attn_kernel, cudaFuncAttributeMaxDynamicSharedMemorySize,
                       ATTN_SMEM);

  convert_w_kernel<<<(3 * C_ * C_) / (256 * 2), 256>>>(qw, kw, vw);
  gemm_mma_kernel<<<dim3(HW_ / 128, C_ / 128, 3 * B_), 256, smem_bytes>>>(
      blue, white, qb, kb, vb);
  attn_kernel<<<dim3(NH, C_ / 8, B_), dim3(32, 8), ATTN_SMEM>>>((float*)d_out);
}

// round 14
// speedup vs baseline: 1.0243x; 1.0243x over previous
#include <cuda_runtime.h>
#include <cuda_fp16.h>
#include <cstdint>

#define B_  2
#define C_  256
#define H_  128
#define W_  128
#define HW_ (H_ * W_)
#define NH  32
#define NW  32

// Q/K/V scratch (fp16, row-major [b][c][h][w])
__device__ __align__(256) __half g_QKV[3][(size_t)B_ * C_ * HW_];

// ---------------------------------------------------------------------------
// Helpers
// ---------------------------------------------------------------------------
__device__ __forceinline__ uint32_t smem_u32(const void* p) {
  uint32_t a;
  asm("{ .reg .u64 t; cvta.to.shared.u64 t, %1; cvt.u32.u64 %0, t; }" : "=r"(a) : "l"(p));
  return a;
}

__device__ __forceinline__ void ldsm_x4(uint32_t* r, uint32_t addr) {
  asm volatile("ldmatrix.sync.aligned.m8n8.x4.shared.b16 {%0,%1,%2,%3}, [%4];"
               : "=r"(r[0]), "=r"(r[1]), "=r"(r[2]), "=r"(r[3]) : "r"(addr));
}
__device__ __forceinline__ void ldsm_x4_t(uint32_t* r, uint32_t addr) {
  asm volatile("ldmatrix.sync.aligned.m8n8.x4.trans.shared.b16 {%0,%1,%2,%3}, [%4];"
               : "=r"(r[0]), "=r"(r[1]), "=r"(r[2]), "=r"(r[3]) : "r"(addr));
}

__device__ __forceinline__ void mma_f16(float* c, const uint32_t* a, const uint32_t* b) {
  asm volatile(
      "mma.sync.aligned.m16n8k16.row.col.f32.f16.f16.f32 "
      "{%0,%1,%2,%3}, {%4,%5,%6,%7}, {%8,%9}, {%0,%1,%2,%3};"
      : "+f"(c[0]), "+f"(c[1]), "+f"(c[2]), "+f"(c[3])
      : "r"(a[0]), "r"(a[1]), "r"(a[2]), "r"(a[3]), "r"(b[0]), "r"(b[1]));
}

// A smem stage-tile: 128 rows x 32 fp16 (64B rows, 4 x 16B chunks, XOR swizzle)
__device__ __forceinline__ uint32_t soff(int r, int c) {
  return (uint32_t)(r * 64 + ((c ^ ((r >> 1) & 3)) << 4));
}
// B smem tile: 32 k-rows x 128 n fp16 (256B rows, 16 x 16B chunks, XOR swizzle)
__device__ __forceinline__ uint32_t boff(int r, int c) {
  return (uint32_t)(r * 256 + ((c ^ (r & 7)) << 4));
}

// smem layout: [A: 8 stage-tiles x 8KB = 64KB][B buf0 8KB][B buf1 8KB] = 80KB
#define SMEM_A      0
#define SMEM_B      65536
#define GEMM_SMEM   81920

__device__ __forceinline__ void cvt8_sts(const float4& f0, const float4& f1,
                                         char* dst) {
  __half2 h[4];
  h[0] = __floats2half2_rn(f0.x, f0.y);
  h[1] = __floats2half2_rn(f0.z, f0.w);
  h[2] = __floats2half2_rn(f1.x, f1.y);
  h[3] = __floats2half2_rn(f1.z, f1.w);
  *(uint4*)dst = *(uint4*)h;
}

// ---------------------------------------------------------------------------
// Kernel 1: single-pass fp16 GEMM via mma.sync (HMMA).
// Prologue converts the CTA's full 128x256 A-slab (fp32 W -> fp16 smem, all
// 8 stage-tiles). Mainloop stages only B (fp32 X -> cvt -> STS), then ldsm +
// MMA exactly as R12. No separate convert kernels at all.
// Out[p][b][m][n] = sum_k W[m][k] * X[k][n] + bias[m]   (fp16 out, row-major)
// ---------------------------------------------------------------------------
__global__ void __launch_bounds__(256, 2) gemm_mma_kernel(
    const float* __restrict__ blue, const float* __restrict__ white,
    const float* __restrict__ qw, const float* __restrict__ kw,
    const float* __restrict__ vw,
    const float* __restrict__ qb, const float* __restrict__ kb,
    const float* __restrict__ vb) {
  extern __shared__ char sm[];
  const uint32_t sbase = smem_u32(sm);

  const int tid = threadIdx.x;
  const int lane = tid & 31;
  const int wid = tid >> 5;
  const int wm = wid >> 2;          // 0..1
  const int wn = wid & 3;           // 0..3

  const int z = blockIdx.z;         // 0..5
  const int p = z >> 1;
  const int b = z & 1;
  const int m0 = blockIdx.y * 128;
  const int n0 = blockIdx.x * 128;

  const float* __restrict__ gWf =
      ((p == 0) ? qw : (p == 1) ? kw : vw) + m0 * C_;
  const float* __restrict__ Xsrc =
      ((p == 0) ? blue : white) + (size_t)b * C_ * HW_ + n0;

  // ---- prologue: convert full A-slab (128 x 256 fp32 -> fp16 smem) ----
  // 4096 8-float segments; 16 per thread. Warp lanes cover one row segment-
  // contiguously (1KB) -> fully coalesced L2-resident loads.
#pragma unroll 4
  for (int it = 0; it < 16; it++) {
    const int idx = it * 256 + tid;
    const int r = idx >> 5;          // 0..127
    const int s = idx & 31;          // 0..31 (8-float segment)
    const float* src = gWf + r * C_ + s * 8;
    float4 f0 = *(const float4*)src;
    float4 f1 = *(const float4*)(src + 4);
    cvt8_sts(f0, f1, sm + SMEM_A + (s >> 2) * 8192 + soff(r, s & 3));
  }

  // B staging: rows tid>>4 (+16), chunk tid&15 (8 floats each)
  const int stg_br = tid >> 4;
  const int stg_bc = tid & 15;

  float acc[4][4][4];
#pragma unroll
  for (int mt = 0; mt < 4; mt++)
#pragma unroll
    for (int nt = 0; nt < 4; nt++)
#pragma unroll
      for (int e = 0; e < 4; e++) acc[mt][nt][e] = 0.f;

  float4 bf[2][2];

#define LDG_B(ks)                                                               \
  {                                                                             \
    const float* bp = Xsrc + (size_t)((ks) * 32) * HW_;                         \
    _Pragma("unroll")                                                           \
    for (int it = 0; it < 2; it++) {                                            \
      const float* q = bp + (size_t)(stg_br + it * 16) * HW_ + stg_bc * 8;      \
      bf[it][0] = *(const float4*)q;                                            \
      bf[it][1] = *(const float4*)(q + 4);                                      \
    }                                                                           \
  }

#define STS_B(buf)                                                              \
  {                                                                             \
    _Pragma("unroll")                                                           \
    for (int it = 0; it < 2; it++)                                              \
      cvt8_sts(bf[it][0], bf[it][1],                                            \
               sm + SMEM_B + (buf) * 8192 + boff(stg_br + it * 16, stg_bc));    \
  }

  LDG_B(0);

  for (int ks = 0; ks < 8; ks++) {
    const int buf = ks & 1;
    STS_B(buf);
    if (ks + 1 < 8) LDG_B(ks + 1);   // prefetch; latency hides under MMAs
    __syncthreads();                  // covers A-prologue (ks=0) + this B tile

    const uint32_t Ab = sbase + SMEM_A + ks * 8192;
    const uint32_t Bb = sbase + SMEM_B + buf * 8192;

#pragma unroll
    for (int kc = 0; kc < 2; kc++) {
      uint32_t ah[4][4], bh[2][4];
      const int arow = wm * 64 + (lane & 15);
      const int achunk = kc * 2 + (lane >> 4);
#pragma unroll
      for (int mt = 0; mt < 4; mt++) {
        int rr = arow + mt * 16;
        ldsm_x4(ah[mt], Ab + soff(rr, achunk));
      }
      const int brow = kc * 16 + ((lane >> 3) & 1) * 8 + (lane & 7);
#pragma unroll
      for (int bt = 0; bt < 2; bt++) {
        int cb = wn * 4 + bt * 2 + (lane >> 4);
        ldsm_x4_t(bh[bt], Bb + boff(brow, cb));
      }
#pragma unroll
      for (int mt = 0; mt < 4; mt++) {
#pragma unroll
        for (int nt = 0; nt < 4; nt++) {
          mma_f16(acc[mt][nt], ah[mt], &bh[nt >> 1][(nt & 1) * 2]);
        }
      }
    }
    __syncthreads();
  }

  // ---- epilogue: bias + fp16 store (row-major, fully coalesced) ----
  const float* __restrict__ biasp = (p == 0) ? qb : (p == 1) ? kb : vb;
  __half* __restrict__ Out = g_QKV[p] + (size_t)b * C_ * HW_;
  const int mrow_base = m0 + wm * 64 + (lane >> 2);
  const int ncol_base = n0 + wn * 32 + (lane & 3) * 2;

#pragma unroll
  for (int mt = 0; mt < 4; mt++) {
    int mr = mrow_base + mt * 16;
    float bi0 = __ldg(biasp + mr);
    float bi1 = __ldg(biasp + mr + 8);
#pragma unroll
    for (int nt = 0; nt < 4; nt++) {
      int nc = ncol_base + nt * 8;
      *(__half2*)(Out + (size_t)mr * HW_ + nc) =
          __floats2half2_rn(acc[mt][nt][0] + bi0, acc[mt][nt][1] + bi0);
      *(__half2*)(Out + (size_t)(mr + 8) * HW_ + nc) =
          __floats2half2_rn(acc[mt][nt][2] + bi1, acc[mt][nt][3] + bi1);
    }
  }
}

// ---------------------------------------------------------------------------
// Kernel 2: per-channel 3x3-neighbor token attention [R12, unchanged].
// Q,K,V fp16 row-major; fused single pass per neighbor; logits in half2
// (HFMA2); no max-subtraction (logits ~N(0,1)); unnormalized fp32 V accum;
// single 1/wsum scale at the end.
// ---------------------------------------------------------------------------
__global__ void __launch_bounds__(256) attn_kernel(float* __restrict__ out) {
  const int j = threadIdx.x;                    // 0..31
  const int i = blockIdx.x;                     // 0..31
  const int c = blockIdx.y * 8 + threadIdx.y;
  const int b = blockIdx.z;

  const size_t base = ((size_t)b * C_ + c) * HW_;
  const __half* __restrict__ Qp = g_QKV[0] + base;
  const __half* __restrict__ Kp = g_QKV[1] + base;
  const __half* __restrict__ Vp = g_QKV[2] + base;

  const int y0 = i * 4;
  const int x0 = j * 4;
  const int tok = y0 * W_ + x0;

  __half2 qh[4][2];
#pragma unroll
  for (int r = 0; r < 4; r++) {
    uint2 u = *(const uint2*)(Qp + tok + r * W_);
    qh[r][0] = *(__half2*)&u.x;
    qh[r][1] = *(__half2*)&u.y;
  }

  float wsum = 0.f;
  float4 o0 = {0, 0, 0, 0}, o1 = {0, 0, 0, 0}, o2 = {0, 0, 0, 0}, o3 = {0, 0, 0, 0};

#pragma unroll
  for (int n = 0; n < 9; n++) {
    const int ii = i + n / 3 - 1;
    const int jj = j + n % 3 - 1;
    if ((unsigned)ii < (unsigned)NH && (unsigned)jj < (unsigned)NW) {
      const int noff = (ii * 4) * W_ + jj * 4;
      const __half* kp = Kp + noff;
      const __half* vp = Vp + noff;
      uint2 k0 = *(const uint2*)(kp);
      uint2 k1 = *(const uint2*)(kp + W_);
      uint2 k2 = *(const uint2*)(kp + 2 * W_);
      uint2 k3 = *(const uint2*)(kp + 3 * W_);
      uint2 v0 = *(const uint2*)(vp);
      uint2 v1 = *(const uint2*)(vp + W_);
      uint2 v2 = *(const uint2*)(vp + 2 * W_);
      uint2 v3 = *(const uint2*)(vp + 3 * W_);

      __half2 acc = __float2half2_rn(0.f);
      acc = __hfma2(qh[0][0], *(__half2*)&k0.x, acc);
      acc = __hfma2(qh[0][1], *(__half2*)&k0.y, acc);
      acc = __hfma2(qh[1][0], *(__half2*)&k1.x, acc);
      acc = __hfma2(qh[1][1], *(__half2*)&k1.y, acc);
      acc = __hfma2(qh[2][0], *(__half2*)&k2.x, acc);
      acc = __hfma2(qh[2][1], *(__half2*)&k2.y, acc);
      acc = __hfma2(qh[3][0], *(__half2*)&k3.x, acc);
      acc = __hfma2(qh[3][1], *(__half2*)&k3.y, acc);
      const float e = __expf((__low2float(acc) + __high2float(acc)) * 0.25f);
      wsum += e;

      float2 f;
      f = __half22float2(*(__half2*)&v0.x); o0.x = fmaf(e, f.x, o0.x); o0.y = fmaf(e, f.y, o0.y);
      f = __half22float2(*(__half2*)&v0.y); o0.z = fmaf(e, f.x, o0.z); o0.w = fmaf(e, f.y, o0.w);
      f = __half22float2(*(__half2*)&v1.x); o1.x = fmaf(e, f.x, o1.x); o1.y = fmaf(e, f.y, o1.y);
      f = __half22float2(*(__half2*)&v1.y); o1.z = fmaf(e, f.x, o1.z); o1.w = fmaf(e, f.y, o1.w);
      f = __half22float2(*(__half2*)&v2.x); o2.x = fmaf(e, f.x, o2.x); o2.y = fmaf(e, f.y, o2.y);
      f = __half22float2(*(__half2*)&v2.y); o2.z = fmaf(e, f.x, o2.z); o2.w = fmaf(e, f.y, o2.w);
      f = __half22float2(*(__half2*)&v3.x); o3.x = fmaf(e, f.x, o3.x); o3.y = fmaf(e, f.y, o3.y);
      f = __half22float2(*(__half2*)&v3.y); o3.z = fmaf(e, f.x, o3.z); o3.w = fmaf(e, f.y, o3.w);
    }
  }

  const float inv = 1.f / wsum;
  o0.x *= inv; o0.y *= inv; o0.z *= inv; o0.w *= inv;
  o1.x *= inv; o1.y *= inv; o1.z *= inv; o1.w *= inv;
  o2.x *= inv; o2.y *= inv; o2.z *= inv; o2.w *= inv;
  o3.x *= inv; o3.y *= inv; o3.z *= inv; o3.w *= inv;

  float* op = out + base + tok;
  *(float4*)(op)          = o0;
  *(float4*)(op + W_)     = o1;
  *(float4*)(op + 2 * W_) = o2;
  *(float4*)(op + 3 * W_) = o3;
}

// ---------------------------------------------------------------------------
extern "C" void kernel_launch(void* const* d_in, const int* in_sizes, int n_in,
                              void* d_out, int out_size) {
  const float* blue  = (const float*)d_in[0];
  const float* white = (const float*)d_in[1];
  const float* qw    = (const float*)d_in[2];
  const float* qb    = (const float*)d_in[3];
  const float* kw    = (const float*)d_in[4];
  const float* kb    = (const float*)d_in[5];
  const float* vw    = (const float*)d_in[6];
  const float* vb    = (const float*)d_in[7];

  cudaFuncSetAttribute(gemm_mma_kernel, cudaFuncAttributeMaxDynamicSharedMemorySize,
                       GEMM_SMEM);

  gemm_mma_kernel<<<dim3(HW_ / 128, C_ / 128, 3 * B_), 256, GEMM_SMEM>>>(
      blue, white, qw, kw, vw, qb, kb, vb);
  attn_kernel<<<dim3(NH, C_ / 8, B_), dim3(32, 8)>>>((float*)d_out);
}

// round 15
// speedup vs baseline: 1.1752x; 1.1473x over previous
#include <cuda_runtime.h>
#include <cuda_fp16.h>
#include <cstdint>

#define B_  2
#define C_  256
#define H_  128
#define W_  128
#define HW_ (H_ * W_)
#define NH  32
#define NW  32

// ---------------------------------------------------------------------------
// Static scratch (no runtime allocation allowed).
// ---------------------------------------------------------------------------
__device__ __align__(256) __half g_Wh[3][C_ * C_];                // fp16(W), [O][K]
__device__ __align__(256) __half g_QKV[3][(size_t)B_ * C_ * HW_]; // Q,K,V fp16 [b][c][hw]

// ---------------------------------------------------------------------------
// Helpers
// ---------------------------------------------------------------------------
__device__ __forceinline__ uint32_t smem_u32(const void* p) {
  uint32_t a;
  asm("{ .reg .u64 t; cvta.to.shared.u64 t, %1; cvt.u32.u64 %0, t; }" : "=r"(a) : "l"(p));
  return a;
}

#define CP_ASYNC16(s, g) \
  asm volatile("cp.async.cg.shared.global [%0], [%1], 16;" :: "r"(s), "l"(g))
#define CP_COMMIT() asm volatile("cp.async.commit_group;" ::: "memory")
#define CP_WAIT0()  asm volatile("cp.async.wait_group 0;" ::: "memory")
#define CP_WAIT1()  asm volatile("cp.async.wait_group 1;" ::: "memory")

__device__ __forceinline__ void ldsm_x4(uint32_t* r, uint32_t addr) {
  asm volatile("ldmatrix.sync.aligned.m8n8.x4.shared.b16 {%0,%1,%2,%3}, [%4];"
               : "=r"(r[0]), "=r"(r[1]), "=r"(r[2]), "=r"(r[3]) : "r"(addr));
}
__device__ __forceinline__ void ldsm_x4_t(uint32_t* r, uint32_t addr) {
  asm volatile("ldmatrix.sync.aligned.m8n8.x4.trans.shared.b16 {%0,%1,%2,%3}, [%4];"
               : "=r"(r[0]), "=r"(r[1]), "=r"(r[2]), "=r"(r[3]) : "r"(addr));
}

__device__ __forceinline__ void mma_f16(float* c, const uint32_t* a, const uint32_t* b) {
  asm volatile(
      "mma.sync.aligned.m16n8k16.row.col.f32.f16.f16.f32 "
      "{%0,%1,%2,%3}, {%4,%5,%6,%7}, {%8,%9}, {%0,%1,%2,%3};"
      : "+f"(c[0]), "+f"(c[1]), "+f"(c[2]), "+f"(c[3])
      : "r"(a[0]), "r"(a[1]), "r"(a[2]), "r"(a[3]), "r"(b[0]), "r"(b[1]));
}

// A smem tile: 128 rows x 32 fp16 (64B rows, 4 x 16B chunks, XOR swizzle)
__device__ __forceinline__ uint32_t soff(int r, int c) {
  return (uint32_t)(r * 64 + ((c ^ ((r >> 1) & 3)) << 4));
}
// B smem tile: 32 k-rows x 128 n fp16 (256B rows, 16 x 16B chunks, XOR swizzle)
__device__ __forceinline__ uint32_t boff(int r, int c) {
  return (uint32_t)(r * 256 + ((c ^ (r & 7)) << 4));
}

// ---------------------------------------------------------------------------
// Kernel 0: weights -> fp16 (vectorized, 8 elems/thread).
// ---------------------------------------------------------------------------
__global__ void __launch_bounds__(256) convert_w_kernel(
    const float* __restrict__ qw, const float* __restrict__ kw,
    const float* __restrict__ vw) {
  int e = (blockIdx.x * 256 + threadIdx.x) * 8;
  int p = e >> 16;
  int r = e & 0xFFFF;
  const float* w = ((p == 0) ? qw : (p == 1) ? kw : vw) + r;
  float4 f0 = *(const float4*)w;
  float4 f1 = *(const float4*)(w + 4);
  __half2 h[4];
  h[0] = __floats2half2_rn(f0.x, f0.y);
  h[1] = __floats2half2_rn(f0.z, f0.w);
  h[2] = __floats2half2_rn(f1.x, f1.y);
  h[3] = __floats2half2_rn(f1.z, f1.w);
  *(uint4*)(g_Wh[p] + r) = *(uint4*)h;
}

// ---------------------------------------------------------------------------
// Kernel 1: single-pass fp16 GEMM via mma.sync (HMMA)  [R12, unchanged].
// A via cp.async from fp16 W; B staged from fp32 X with in-kernel conversion.
// Out[p][b][m][n] = sum_k W[m][k] * X[k][n] + bias[m]   (fp16 out, row-major)
// CTA: 128(m) x 128(n), BK=32, 8 warps (2x4), warp 64x32, double-buffered.
// ---------------------------------------------------------------------------
__global__ void __launch_bounds__(256, 2) gemm_mma_kernel(
    const float* __restrict__ blue, const float* __restrict__ white,
    const float* __restrict__ qb, const float* __restrict__ kb,
    const float* __restrict__ vb) {
  extern __shared__ char sm[];
  const uint32_t sbase = smem_u32(sm);

  const int tid = threadIdx.x;
  const int lane = tid & 31;
  const int wid = tid >> 5;
  const int wm = wid >> 2;
  const int wn = wid & 3;

  const int z = blockIdx.z;
  const int p = z >> 1;
  const int b = z & 1;
  const int m0 = blockIdx.y * 128;
  const int n0 = blockIdx.x * 128;

  const __half* __restrict__ gA = g_Wh[p] + m0 * C_;
  const float* __restrict__ Xsrc =
      ((p == 0) ? blue : white) + (size_t)b * C_ * HW_ + n0;

  const int stg_ar = tid >> 2;
  const int stg_ac = tid & 3;
  const int stg_br = tid >> 4;
  const int stg_bc = tid & 15;

  float acc[4][4][4];
#pragma unroll
  for (int mt = 0; mt < 4; mt++)
#pragma unroll
    for (int nt = 0; nt < 4; nt++)
#pragma unroll
      for (int e = 0; e < 4; e++) acc[mt][nt][e] = 0.f;

  float4 bf[2][2];

#define ISSUE_A(ks, buf)                                                        \
  {                                                                             \
    const int k0 = (ks) * 32;                                                   \
    _Pragma("unroll")                                                           \
    for (int it = 0; it < 2; it++) {                                            \
      int r = stg_ar + it * 64;                                                 \
      CP_ASYNC16(sbase + (buf) * 16384 + soff(r, stg_ac),                       \
                 gA + r * C_ + k0 + stg_ac * 8);                                \
    }                                                                           \
    CP_COMMIT();                                                                \
  }

#define LDG_B(ks)                                                               \
  {                                                                             \
    const float* bp = Xsrc + (size_t)((ks) * 32) * HW_;                         \
    _Pragma("unroll")                                                           \
    for (int it = 0; it < 2; it++) {                                            \
      const float* q = bp + (size_t)(stg_br + it * 16) * HW_ + stg_bc * 8;      \
      bf[it][0] = *(const float4*)q;                                            \
      bf[it][1] = *(const float4*)(q + 4);                                      \
    }                                                                           \
  }

#define STS_B(buf)                                                              \
  {                                                                             \
    _Pragma("unroll")                                                           \
    for (int it = 0; it < 2; it++) {                                            \
      int r = stg_br + it * 16;                                                 \
      __half2 h[4];                                                             \
      h[0] = __floats2half2_rn(bf[it][0].x, bf[it][0].y);                       \
      h[1] = __floats2half2_rn(bf[it][0].z, bf[it][0].w);                       \
      h[2] = __floats2half2_rn(bf[it][1].x, bf[it][1].y);                       \
      h[3] = __floats2half2_rn(bf[it][1].z, bf[it][1].w);                       \
      *(uint4*)(sm + (buf) * 16384 + 8192 + boff(r, stg_bc)) = *(uint4*)h;      \
    }                                                                           \
  }

  ISSUE_A(0, 0);
  LDG_B(0);

  for (int ks = 0; ks < 8; ks++) {
    const int buf = ks & 1;
    STS_B(buf);
    if (ks + 1 < 8) {
      LDG_B(ks + 1);
      ISSUE_A(ks + 1, buf ^ 1);
      CP_WAIT1();
    } else {
      CP_WAIT0();
    }
    __syncthreads();

    const uint32_t Ab = sbase + buf * 16384;
    const uint32_t Bb = Ab + 8192;

#pragma unroll
    for (int kc = 0; kc < 2; kc++) {
      uint32_t ah[4][4], bh[2][4];
      const int arow = wm * 64 + (lane & 15);
      const int achunk = kc * 2 + (lane >> 4);
#pragma unroll
      for (int mt = 0; mt < 4; mt++) {
        int rr = arow + mt * 16;
        ldsm_x4(ah[mt], Ab + soff(rr, achunk));
      }
      const int brow = kc * 16 + ((lane >> 3) & 1) * 8 + (lane & 7);
#pragma unroll
      for (int bt = 0; bt < 2; bt++) {
        int cb = wn * 4 + bt * 2 + (lane >> 4);
        ldsm_x4_t(bh[bt], Bb + boff(brow, cb));
      }
#pragma unroll
      for (int mt = 0; mt < 4; mt++) {
#pragma unroll
        for (int nt = 0; nt < 4; nt++) {
          mma_f16(acc[mt][nt], ah[mt], &bh[nt >> 1][(nt & 1) * 2]);
        }
      }
    }
    __syncthreads();
  }

  const float* __restrict__ biasp = (p == 0) ? qb : (p == 1) ? kb : vb;
  __half* __restrict__ Out = g_QKV[p] + (size_t)b * C_ * HW_;
  const int mrow_base = m0 + wm * 64 + (lane >> 2);
  const int ncol_base = n0 + wn * 32 + (lane & 3) * 2;

#pragma unroll
  for (int mt = 0; mt < 4; mt++) {
    int mr = mrow_base + mt * 16;
    float bi0 = __ldg(biasp + mr);
    float bi1 = __ldg(biasp + mr + 8);
#pragma unroll
    for (int nt = 0; nt < 4; nt++) {
      int nc = ncol_base + nt * 8;
      *(__half2*)(Out + (size_t)mr * HW_ + nc) =
          __floats2half2_rn(acc[mt][nt][0] + bi0, acc[mt][nt][1] + bi0);
      *(__half2*)(Out + (size_t)(mr + 8) * HW_ + nc) =
          __floats2half2_rn(acc[mt][nt][2] + bi1, acc[mt][nt][3] + bi1);
    }
  }
}

// ---------------------------------------------------------------------------
// Kernel 2: per-channel 3x3-neighbor token attention [R12 + exp2 micro-opt].
// Q,K,V fp16 row-major; fused single pass per neighbor; logits in half2
// (HFMA2); no max-subtraction (logits ~N(0,1)); unnormalized fp32 V accum;
// single 1/wsum scale. exp computed as exp2f(logit * (0.25*log2(e))) -- one
// FMUL feeding MUFU.EX2 instead of scale-mul + expf's internal mul.
// ---------------------------------------------------------------------------
__global__ void __launch_bounds__(256) attn_kernel(float* __restrict__ out) {
  const int j = threadIdx.x;                    // 0..31
  const int i = blockIdx.x;                     // 0..31
  const int c = blockIdx.y * 8 + threadIdx.y;
  const int b = blockIdx.z;

  const size_t base = ((size_t)b * C_ + c) * HW_;
  const __half* __restrict__ Qp = g_QKV[0] + base;
  const __half* __restrict__ Kp = g_QKV[1] + base;
  const __half* __restrict__ Vp = g_QKV[2] + base;

  const int tok = (i * 4) * W_ + j * 4;
  const float SC = 0.25f * 1.4426950408889634f;   // SCALE * log2(e)

  __half2 qh[4][2];
#pragma unroll
  for (int r = 0; r < 4; r++) {
    uint2 u = *(const uint2*)(Qp + tok + r * W_);
    qh[r][0] = *(__half2*)&u.x;
    qh[r][1] = *(__half2*)&u.y;
  }

  float wsum = 0.f;
  float4 o0 = {0, 0, 0, 0}, o1 = {0, 0, 0, 0}, o2 = {0, 0, 0, 0}, o3 = {0, 0, 0, 0};

#pragma unroll
  for (int n = 0; n < 9; n++) {
    const int ii = i + n / 3 - 1;
    const int jj = j + n % 3 - 1;
    if ((unsigned)ii < (unsigned)NH && (unsigned)jj < (unsigned)NW) {
      const int noff = (ii * 4) * W_ + jj * 4;
      const __half* kp = Kp + noff;
      const __half* vp = Vp + noff;
      uint2 k0 = *(const uint2*)(kp);
      uint2 k1 = *(const uint2*)(kp + W_);
      uint2 k2 = *(const uint2*)(kp + 2 * W_);
      uint2 k3 = *(const uint2*)(kp + 3 * W_);
      uint2 v0 = *(const uint2*)(vp);
      uint2 v1 = *(const uint2*)(vp + W_);
      uint2 v2 = *(const uint2*)(vp + 2 * W_);
      uint2 v3 = *(const uint2*)(vp + 3 * W_);

      __half2 acc = __float2half2_rn(0.f);
      acc = __hfma2(qh[0][0], *(__half2*)&k0.x, acc);
      acc = __hfma2(qh[0][1], *(__half2*)&k0.y, acc);
      acc = __hfma2(qh[1][0], *(__half2*)&k1.x, acc);
      acc = __hfma2(qh[1][1], *(__half2*)&k1.y, acc);
      acc = __hfma2(qh[2][0], *(__half2*)&k2.x, acc);
      acc = __hfma2(qh[2][1], *(__half2*)&k2.y, acc);
      acc = __hfma2(qh[3][0], *(__half2*)&k3.x, acc);
      acc = __hfma2(qh[3][1], *(__half2*)&k3.y, acc);
      const float e = exp2f((__low2float(acc) + __high2float(acc)) * SC);
      wsum += e;

      float2 f;
      f = __half22float2(*(__half2*)&v0.x); o0.x = fmaf(e, f.x, o0.x); o0.y = fmaf(e, f.y, o0.y);
      f = __half22float2(*(__half2*)&v0.y); o0.z = fmaf(e, f.x, o0.z); o0.w = fmaf(e, f.y, o0.w);
      f = __half22float2(*(__half2*)&v1.x); o1.x = fmaf(e, f.x, o1.x); o1.y = fmaf(e, f.y, o1.y);
      f = __half22float2(*(__half2*)&v1.y); o1.z = fmaf(e, f.x, o1.z); o1.w = fmaf(e, f.y, o1.w);
      f = __half22float2(*(__half2*)&v2.x); o2.x = fmaf(e, f.x, o2.x); o2.y = fmaf(e, f.y, o2.y);
      f = __half22float2(*(__half2*)&v2.y); o2.z = fmaf(e, f.x, o2.z); o2.w = fmaf(e, f.y, o2.w);
      f = __half22float2(*(__half2*)&v3.x); o3.x = fmaf(e, f.x, o3.x); o3.y = fmaf(e, f.y, o3.y);
      f = __half22float2(*(__half2*)&v3.y); o3.z = fmaf(e, f.x, o3.z); o3.w = fmaf(e, f.y, o3.w);
    }
  }

  const float inv = 1.f / wsum;
  o0.x *= inv; o0.y *= inv; o0.z *= inv; o0.w *= inv;
  o1.x *= inv; o1.y *= inv; o1.z *= inv; o1.w *= inv;
  o2.x *= inv; o2.y *= inv; o2.z *= inv; o2.w *= inv;
  o3.x *= inv; o3.y *= inv; o3.z *= inv; o3.w *= inv;

  float* op = out + base + tok;
  *(float4*)(op)          = o0;
  *(float4*)(op + W_)     = o1;
  *(float4*)(op + 2 * W_) = o2;
  *(float4*)(op + 3 * W_) = o3;
}

// ---------------------------------------------------------------------------
extern "C" void kernel_launch(void* const* d_in, const int* in_sizes, int n_in,
                              void* d_out, int out_size) {
  const float* blue  = (const float*)d_in[0];
  const float* white = (const float*)d_in[1];
  const float* qw    = (const float*)d_in[2];
  const float* qb    = (const float*)d_in[3];
  const float* kw    = (const float*)d_in[4];
  const float* kb    = (const float*)d_in[5];
  const float* vw    = (const float*)d_in[6];
  const float* vb    = (const float*)d_in[7];

  const int smem_bytes = 32768;
  cudaFuncSetAttribute(gemm_mma_kernel, cudaFuncAttributeMaxDynamicSharedMemorySize,
                       smem_bytes);

  convert_w_kernel<<<(3 * C_ * C_) / (256 * 8), 256>>>(qw, kw, vw);
  gemm_mma_kernel<<<dim3(HW_ / 128, C_ / 128, 3 * B_), 256, smem_bytes>>>(
      blue, white, qb, kb, vb);
  attn_kernel<<<dim3(NH, C_ / 8, B_), dim3(32, 8)>>>((float*)d_out);
}

// round 16
// speedup vs baseline: 1.1770x; 1.0016x over previous
#include <cuda_runtime.h>
#include <cuda_fp16.h>
#include <cstdint>

#define B_  2
#define C_  256
#define H_  128
#define W_  128
#define HW_ (H_ * W_)
#define NH  32
#define NW  32

// ---------------------------------------------------------------------------
// Static scratch (no runtime allocation allowed).
// ---------------------------------------------------------------------------
__device__ __align__(256) __half g_Wh[3][C_ * C_];                // fp16(W), [O][K]
__device__ __align__(256) __half g_QKV[3][(size_t)B_ * C_ * HW_]; // Q,K,V fp16 [b][c][hw]

// ---------------------------------------------------------------------------
// Helpers
// ---------------------------------------------------------------------------
__device__ __forceinline__ uint32_t smem_u32(const void* p) {
  uint32_t a;
  asm("{ .reg .u64 t; cvta.to.shared.u64 t, %1; cvt.u32.u64 %0, t; }" : "=r"(a) : "l"(p));
  return a;
}

#define CP_ASYNC16(s, g) \
  asm volatile("cp.async.cg.shared.global [%0], [%1], 16;" :: "r"(s), "l"(g))
#define CP_COMMIT() asm volatile("cp.async.commit_group;" ::: "memory")
#define CP_WAIT0()  asm volatile("cp.async.wait_group 0;" ::: "memory")

__device__ __forceinline__ void ldsm_x4(uint32_t* r, uint32_t addr) {
  asm volatile("ldmatrix.sync.aligned.m8n8.x4.shared.b16 {%0,%1,%2,%3}, [%4];"
               : "=r"(r[0]), "=r"(r[1]), "=r"(r[2]), "=r"(r[3]) : "r"(addr));
}
__device__ __forceinline__ void ldsm_x4_t(uint32_t* r, uint32_t addr) {
  asm volatile("ldmatrix.sync.aligned.m8n8.x4.trans.shared.b16 {%0,%1,%2,%3}, [%4];"
               : "=r"(r[0]), "=r"(r[1]), "=r"(r[2]), "=r"(r[3]) : "r"(addr));
}

__device__ __forceinline__ void mma_f16(float* c, const uint32_t* a, const uint32_t* b) {
  asm volatile(
      "mma.sync.aligned.m16n8k16.row.col.f32.f16.f16.f32 "
      "{%0,%1,%2,%3}, {%4,%5,%6,%7}, {%8,%9}, {%0,%1,%2,%3};"
      : "+f"(c[0]), "+f"(c[1]), "+f"(c[2]), "+f"(c[3])
      : "r"(a[0]), "r"(a[1]), "r"(a[2]), "r"(a[3]), "r"(b[0]), "r"(b[1]));
}

// A smem tile: 128 rows x 32 fp16 (64B rows, 4 x 16B chunks, XOR swizzle)
__device__ __forceinline__ uint32_t soff(int r, int c) {
  return (uint32_t)(r * 64 + ((c ^ ((r >> 1) & 3)) << 4));
}
// B smem tile: 32 k-rows x 128 n fp16 (256B rows, 16 x 16B chunks, XOR swizzle)
__device__ __forceinline__ uint32_t boff(int r, int c) {
  return (uint32_t)(r * 256 + ((c ^ (r & 7)) << 4));
}

// ---------------------------------------------------------------------------
// Kernel 0: weights -> fp16 (vectorized, 8 elems/thread).
// ---------------------------------------------------------------------------
__global__ void __launch_bounds__(256) convert_w_kernel(
    const float* __restrict__ qw, const float* __restrict__ kw,
    const float* __restrict__ vw) {
  int e = (blockIdx.x * 256 + threadIdx.x) * 8;
  int p = e >> 16;
  int r = e & 0xFFFF;
  const float* w = ((p == 0) ? qw : (p == 1) ? kw : vw) + r;
  float4 f0 = *(const float4*)w;
  float4 f1 = *(const float4*)(w + 4);
  __half2 h[4];
  h[0] = __floats2half2_rn(f0.x, f0.y);
  h[1] = __floats2half2_rn(f0.z, f0.w);
  h[2] = __floats2half2_rn(f1.x, f1.y);
  h[3] = __floats2half2_rn(f1.z, f1.w);
  *(uint4*)(g_Wh[p] + r) = *(uint4*)h;
}

// ---------------------------------------------------------------------------
// Kernel 1: single-pass fp16 GEMM via mma.sync (HMMA).
// R12 layout/fragments, restructured pipeline: ONE __syncthreads per K-stage;
// B's cvt+STS and A's cp.async for stage ks+1 overlap the MMA of stage ks
// (they target the other buffer).
// Out[p][b][m][n] = sum_k W[m][k] * X[k][n] + bias[m]   (fp16 out, row-major)
// CTA: 128(m) x 128(n), BK=32, 8 warps (2x4), warp 64x32, double-buffered.
// ---------------------------------------------------------------------------
__global__ void __launch_bounds__(256, 2) gemm_mma_kernel(
    const float* __restrict__ blue, const float* __restrict__ white,
    const float* __restrict__ qb, const float* __restrict__ kb,
    const float* __restrict__ vb) {
  extern __shared__ char sm[];
  const uint32_t sbase = smem_u32(sm);

  const int tid = threadIdx.x;
  const int lane = tid & 31;
  const int wid = tid >> 5;
  const int wm = wid >> 2;
  const int wn = wid & 3;

  const int z = blockIdx.z;
  const int p = z >> 1;
  const int b = z & 1;
  const int m0 = blockIdx.y * 128;
  const int n0 = blockIdx.x * 128;

  const __half* __restrict__ gA = g_Wh[p] + m0 * C_;
  const float* __restrict__ Xsrc =
      ((p == 0) ? blue : white) + (size_t)b * C_ * HW_ + n0;

  const int stg_ar = tid >> 2;
  const int stg_ac = tid & 3;
  const int stg_br = tid >> 4;
  const int stg_bc = tid & 15;

  float acc[4][4][4];
#pragma unroll
  for (int mt = 0; mt < 4; mt++)
#pragma unroll
    for (int nt = 0; nt < 4; nt++)
#pragma unroll
      for (int e = 0; e < 4; e++) acc[mt][nt][e] = 0.f;

  float4 bf[2][2];

#define ISSUE_A(ks, buf)                                                        \
  {                                                                             \
    const int k0 = (ks) * 32;                                                   \
    _Pragma("unroll")                                                           \
    for (int it = 0; it < 2; it++) {                                            \
      int r = stg_ar + it * 64;                                                 \
      CP_ASYNC16(sbase + (buf) * 16384 + soff(r, stg_ac),                       \
                 gA + r * C_ + k0 + stg_ac * 8);                                \
    }                                                                           \
    CP_COMMIT();                                                                \
  }

#define LDG_B(ks)                                                               \
  {                                                                             \
    const float* bp = Xsrc + (size_t)((ks) * 32) * HW_;                         \
    _Pragma("unroll")                                                           \
    for (int it = 0; it < 2; it++) {                                            \
      const float* q = bp + (size_t)(stg_br + it * 16) * HW_ + stg_bc * 8;      \
      bf[it][0] = *(const float4*)q;                                            \
      bf[it][1] = *(const float4*)(q + 4);                                      \
    }                                                                           \
  }

#define STS_B(buf)                                                              \
  {                                                                             \
    _Pragma("unroll")                                                           \
    for (int it = 0; it < 2; it++) {                                            \
      int r = stg_br + it * 16;                                                 \
      __half2 h[4];                                                             \
      h[0] = __floats2half2_rn(bf[it][0].x, bf[it][0].y);                       \
      h[1] = __floats2half2_rn(bf[it][0].z, bf[it][0].w);                       \
      h[2] = __floats2half2_rn(bf[it][1].x, bf[it][1].y);                       \
      h[3] = __floats2half2_rn(bf[it][1].z, bf[it][1].w);                       \
      *(uint4*)(sm + (buf) * 16384 + 8192 + boff(r, stg_bc)) = *(uint4*)h;      \
    }                                                                           \
  }

  // ---- prologue: fill buffer 0 ----
  ISSUE_A(0, 0);
  LDG_B(0);
  STS_B(0);
  CP_WAIT0();
  __syncthreads();

  // ---- mainloop: one sync per stage; staging of ks+1 overlaps MMA of ks ----
  for (int ks = 0; ks < 8; ks++) {
    const int buf = ks & 1;

    if (ks + 1 < 8) {
      ISSUE_A(ks + 1, buf ^ 1);   // async into other buffer
      LDG_B(ks + 1);              // gmem loads; latency covered by MMAs below
    }

    const uint32_t Ab = sbase + buf * 16384;
    const uint32_t Bb = Ab + 8192;

#pragma unroll
    for (int kc = 0; kc < 2; kc++) {
      uint32_t ah[4][4], bh[2][4];
      const int arow = wm * 64 + (lane & 15);
      const int achunk = kc * 2 + (lane >> 4);
#pragma unroll
      for (int mt = 0; mt < 4; mt++) {
        int rr = arow + mt * 16;
        ldsm_x4(ah[mt], Ab + soff(rr, achunk));
      }
      const int brow = kc * 16 + ((lane >> 3) & 1) * 8 + (lane & 7);
#pragma unroll
      for (int bt = 0; bt < 2; bt++) {
        int cb = wn * 4 + bt * 2 + (lane >> 4);
        ldsm_x4_t(bh[bt], Bb + boff(brow, cb));
      }
#pragma unroll
      for (int mt = 0; mt < 4; mt++) {
#pragma unroll
        for (int nt = 0; nt < 4; nt++) {
          mma_f16(acc[mt][nt], ah[mt], &bh[nt >> 1][(nt & 1) * 2]);
        }
      }
    }

    if (ks + 1 < 8) {
      STS_B(buf ^ 1);             // writes other buffer -- safe pre-sync
      CP_WAIT0();                 // A(ks+1) cp.async complete
    }
    __syncthreads();
  }

  // ---- epilogue: bias + fp16 store (row-major, fully coalesced) ----
  const float* __restrict__ biasp = (p == 0) ? qb : (p == 1) ? kb : vb;
  __half* __restrict__ Out = g_QKV[p] + (size_t)b * C_ * HW_;
  const int mrow_base = m0 + wm * 64 + (lane >> 2);
  const int ncol_base = n0 + wn * 32 + (lane & 3) * 2;

#pragma unroll
  for (int mt = 0; mt < 4; mt++) {
    int mr = mrow_base + mt * 16;
    float bi0 = __ldg(biasp + mr);
    float bi1 = __ldg(biasp + mr + 8);
#pragma unroll
    for (int nt = 0; nt < 4; nt++) {
      int nc = ncol_base + nt * 8;
      *(__half2*)(Out + (size_t)mr * HW_ + nc) =
          __floats2half2_rn(acc[mt][nt][0] + bi0, acc[mt][nt][1] + bi0);
      *(__half2*)(Out + (size_t)(mr + 8) * HW_ + nc) =
          __floats2half2_rn(acc[mt][nt][2] + bi1, acc[mt][nt][3] + bi1);
    }
  }
}

// ---------------------------------------------------------------------------
// Kernel 2: per-channel 3x3-neighbor token attention [R12, unchanged].
// ---------------------------------------------------------------------------
__global__ void __launch_bounds__(256) attn_kernel(float* __restrict__ out) {
  const int j = threadIdx.x;                    // 0..31
  const int i = blockIdx.x;                     // 0..31
  const int c = blockIdx.y * 8 + threadIdx.y;
  const int b = blockIdx.z;

  const size_t base = ((size_t)b * C_ + c) * HW_;
  const __half* __restrict__ Qp = g_QKV[0] + base;
  const __half* __restrict__ Kp = g_QKV[1] + base;
  const __half* __restrict__ Vp = g_QKV[2] + base;

  const int tok = (i * 4) * W_ + j * 4;

  __half2 qh[4][2];
#pragma unroll
  for (int r = 0; r < 4; r++) {
    uint2 u = *(const uint2*)(Qp + tok + r * W_);
    qh[r][0] = *(__half2*)&u.x;
    qh[r][1] = *(__half2*)&u.y;
  }

  float wsum = 0.f;
  float4 o0 = {0, 0, 0, 0}, o1 = {0, 0, 0, 0}, o2 = {0, 0, 0, 0}, o3 = {0, 0, 0, 0};

#pragma unroll
  for (int n = 0; n < 9; n++) {
    const int ii = i + n / 3 - 1;
    const int jj = j + n % 3 - 1;
    if ((unsigned)ii < (unsigned)NH && (unsigned)jj < (unsigned)NW) {
      const int noff = (ii * 4) * W_ + jj * 4;
      const __half* kp = Kp + noff;
      const __half* vp = Vp + noff;
      uint2 k0 = *(const uint2*)(kp);
      uint2 k1 = *(const uint2*)(kp + W_);
      uint2 k2 = *(const uint2*)(kp + 2 * W_);
      uint2 k3 = *(const uint2*)(kp + 3 * W_);
      uint2 v0 = *(const uint2*)(vp);
      uint2 v1 = *(const uint2*)(vp + W_);
      uint2 v2 = *(const uint2*)(vp + 2 * W_);
      uint2 v3 = *(const uint2*)(vp + 3 * W_);

      __half2 acc = __float2half2_rn(0.f);
      acc = __hfma2(qh[0][0], *(__half2*)&k0.x, acc);
      acc = __hfma2(qh[0][1], *(__half2*)&k0.y, acc);
      acc = __hfma2(qh[1][0], *(__half2*)&k1.x, acc);
      acc = __hfma2(qh[1][1], *(__half2*)&k1.y, acc);
      acc = __hfma2(qh[2][0], *(__half2*)&k2.x, acc);
      acc = __hfma2(qh[2][1], *(__half2*)&k2.y, acc);
      acc = __hfma2(qh[3][0], *(__half2*)&k3.x, acc);
      acc = __hfma2(qh[3][1], *(__half2*)&k3.y, acc);
      const float e = __expf((__low2float(acc) + __high2float(acc)) * 0.25f);
      wsum += e;

      float2 f;
      f = __half22float2(*(__half2*)&v0.x); o0.x = fmaf(e, f.x, o0.x); o0.y = fmaf(e, f.y, o0.y);
      f = __half22float2(*(__half2*)&v0.y); o0.z = fmaf(e, f.x, o0.z); o0.w = fmaf(e, f.y, o0.w);
      f = __half22float2(*(__half2*)&v1.x); o1.x = fmaf(e, f.x, o1.x); o1.y = fmaf(e, f.y, o1.y);
      f = __half22float2(*(__half2*)&v1.y); o1.z = fmaf(e, f.x, o1.z); o1.w = fmaf(e, f.y, o1.w);
      f = __half22float2(*(__half2*)&v2.x); o2.x = fmaf(e, f.x, o2.x); o2.y = fmaf(e, f.y, o2.y);
      f = __half22float2(*(__half2*)&v2.y); o2.z = fmaf(e, f.x, o2.z); o2.w = fmaf(e, f.y, o2.w);
      f = __half22float2(*(__half2*)&v3.x); o3.x = fmaf(e, f.x, o3.x); o3.y = fmaf(e, f.y, o3.y);
      f = __half22float2(*(__half2*)&v3.y); o3.z = fmaf(e, f.x, o3.z); o3.w = fmaf(e, f.y, o3.w);
    }
  }

  const float inv = 1.f / wsum;
  o0.x *= inv; o0.y *= inv; o0.z *= inv; o0.w *= inv;
  o1.x *= inv; o1.y *= inv; o1.z *= inv; o1.w *= inv;
  o2.x *= inv; o2.y *= inv; o2.z *= inv; o2.w *= inv;
  o3.x *= inv; o3.y *= inv; o3.z *= inv; o3.w *= inv;

  float* op = out + base + tok;
  *(float4*)(op)          = o0;
  *(float4*)(op + W_)     = o1;
  *(float4*)(op + 2 * W_) = o2;
  *(float4*)(op + 3 * W_) = o3;
}

// ---------------------------------------------------------------------------
extern "C" void kernel_launch(void* const* d_in, const int* in_sizes, int n_in,
                              void* d_out, int out_size) {
  const float* blue  = (const float*)d_in[0];
  const float* white = (const float*)d_in[1];
  const float* qw    = (const float*)d_in[2];
  const float* qb    = (const float*)d_in[3];
  const float* kw    = (const float*)d_in[4];
  const float* kb    = (const float*)d_in[5];
  const float* vw    = (const float*)d_in[6];
  const float* vb    = (const float*)d_in[7];

  const int smem_bytes = 32768;
  cudaFuncSetAttribute(gemm_mma_kernel, cudaFuncAttributeMaxDynamicSharedMemorySize,
                       smem_bytes);

  convert_w_kernel<<<(3 * C_ * C_) / (256 * 8), 256>>>(qw, kw, vw);
  gemm_mma_kernel<<<dim3(HW_ / 128, C_ / 128, 3 * B_), 256, smem_bytes>>>(
      blue, white, qb, kb, vb);
  attn_kernel<<<dim3(NH, C_ / 8, B_), dim3(32, 8)>>>((float*)d_out);
}